// round 16
// baseline (speedup 1.0000x reference)
#include <cuda_runtime.h>
#include <cuda_fp16.h>
#include <cstdint>

#define NLOC  384
#define DHID  32
#define DPAIR 64
#define NCOL  (NLOC * DPAIR)   // 24576

// ---------------- scratch (static device globals; no allocations) ----------
__device__ __align__(16) __half g_Ah[NLOC * DHID];  // a fp16           [384][32]
__device__ __align__(16) __half g_Ch[NCOL * DHID];  // C*op_norm fp16   [24576][32]

// ---------------- helpers ---------------------------------------------------
__device__ __forceinline__ uint32_t smem_u32(const void* p) {
    uint32_t a;
    asm("{ .reg .u64 t; cvta.to.shared.u64 t, %1; cvt.u32.u64 %0, t; }"
        : "=r"(a) : "l"(p));
    return a;
}
__device__ __forceinline__ void ldsm_x4(uint32_t* r, uint32_t addr) {
    asm volatile("ldmatrix.sync.aligned.m8n8.x4.shared.b16 {%0,%1,%2,%3}, [%4];"
                 : "=r"(r[0]), "=r"(r[1]), "=r"(r[2]), "=r"(r[3]) : "r"(addr));
}
__device__ __forceinline__ void mma_f16(float* d, const uint32_t* a,
                                        const uint32_t* b) {
    asm volatile(
        "mma.sync.aligned.m16n8k16.row.col.f32.f16.f16.f32 "
        "{%0,%1,%2,%3}, {%4,%5,%6,%7}, {%8,%9}, {%0,%1,%2,%3};"
        : "+f"(d[0]), "+f"(d[1]), "+f"(d[2]), "+f"(d[3])
        : "r"(a[0]), "r"(a[1]), "r"(a[2]), "r"(a[3]), "r"(b[0]), "r"(b[1]));
}
__device__ __forceinline__ void stcs4(float* p, float4 v) {
    asm volatile("st.global.cs.v4.f32 [%0], {%1, %2, %3, %4};"
                 :: "l"(p), "f"(v.x), "f"(v.y), "f"(v.z), "f"(v.w) : "memory");
}
__device__ __forceinline__ void cp16(uint32_t dst, const void* src) {
    asm volatile("cp.async.cg.shared.global [%0], [%1], 16;"
                 :: "r"(dst), "l"(src) : "memory");
}
#define CP_COMMIT() asm volatile("cp.async.commit_group;" ::: "memory")
#define CP_WAIT0()  asm volatile("cp.async.wait_group 0;" ::: "memory")

// 8-chain float4 dot-product step (two f4 pairs per iteration)
#define DOT8(A0, A1, mr, wr, c)                                   \
    {   float4 mv0 = (mr)[c],     wv0 = (wr)[c];                  \
        float4 mv1 = (mr)[(c)+1], wv1 = (wr)[(c)+1];              \
        A0.x += mv0.x * wv0.x; A0.y += mv0.y * wv0.y;             \
        A0.z += mv0.z * wv0.z; A0.w += mv0.w * wv0.w;             \
        A1.x += mv1.x * wv1.x; A1.y += mv1.y * wv1.y;             \
        A1.z += mv1.z * wv1.z; A1.w += mv1.w * wv1.w; }

// ---------------- kernel 12: fused A-projection + C-build -------------------
// C role (blocks 0..383):  rt = bid & 7, j0 = (bid>>3)*8
// A role (blocks 384..407): n0 = (bid-384)*16
// dyn smem floats: W_t[0,9216) stride36 | m4[9216,+2048) | W4[11264,+4224) | b_s[15488,+512)
#define K12_WT   0
#define K12_MS   9216
#define K12_WS   11264
#define K12_BS   15488
#define K12_SMEM (16000 * 4)

__global__ __launch_bounds__(256) void k12(
        const float* __restrict__ m,
        const float* __restrict__ W_in,
        const float* __restrict__ b_in,
        const float* __restrict__ op_mask,
        const float* __restrict__ op_norm,
        const float* __restrict__ W_out)
{
    extern __shared__ float S[];
    const int tid = threadIdx.x;
    const int bid = blockIdx.x;
    const float4* Mg4 = (const float4*)m;
    const float4* Wg4 = (const float4*)W_in;

    if (bid >= 384) {
        // ---------------- A role ----------------
        const int n0 = (bid - 384) * 16;
        float4* m4 = (float4*)(S + K12_MS);   // [16][32]
        float4* w4 = (float4*)(S + K12_WS);   // [32][33] (stride 33 f4: conflict-free)
        #pragma unroll
        for (int i = 0; i < 2; ++i) {
            int e = tid + i * 256;            // 512 f4 of m
            int row = e >> 5, q = e & 31;
            m4[row * 32 + q] = Mg4[(size_t)(n0 + row) * 32 + q];
        }
        #pragma unroll
        for (int i = 0; i < 4; ++i) {         // W_in rows 0..31 = 1024 f4
            int e = tid + i * 256;
            w4[(e >> 5) * 33 + (e & 31)] = Wg4[e];
        }
        __syncthreads();

        const float opm = op_mask[0];
        #pragma unroll
        for (int half = 0; half < 2; ++half) {
            int t  = tid + half * 256;
            int rl = t >> 5, h = t & 31;      // h == lane -> stride-33 f4 rows
            const float4* mr = m4 + rl * 32;
            const float4* wr = w4 + h * 33;
            float4 A0 = make_float4(0.f, 0.f, 0.f, 0.f);
            float4 A1 = make_float4(0.f, 0.f, 0.f, 0.f);
            #pragma unroll
            for (int c = 0; c < 32; c += 2) DOT8(A0, A1, mr, wr, c);
            float v = ((A0.x + A0.y) + (A0.z + A0.w)
                     + (A1.x + A1.y) + (A1.z + A1.w) + b_in[h]) * opm;
            g_Ah[(n0 + rl) * DHID + h] = __float2half_rn(v);
        }
        cudaTriggerProgrammaticLaunchCompletion();
        return;
    }

    // ---------------- C role: 8 j-rows per block ----------------
    const int rt = bid & 7;
    const int j0 = (bid >> 3) * 8;

    {   // cp.async W_out slice (32 KB), stride-36 rows
        const uint32_t wt_b = smem_u32(S + K12_WT);
        #pragma unroll
        for (int i = 0; i < 8; ++i) {
            int e = tid + i * 256;
            int row = e >> 3, chk = e & 7;
            cp16(wt_b + (row * 36 + chk * 4) * 4,
                 W_out + (size_t)rt * 8192 + row * 32 + chk * 4);
        }
        CP_COMMIT();
    }

    float4* m4 = (float4*)(S + K12_MS);       // [8][32]
    float4* w4 = (float4*)(S + K12_WS);       // [32][33]
    float*  b_s = S + K12_BS;
    {   // m rows j0..j0+7: 256 f4, one per thread (tid == row*32+q)
        m4[tid] = Mg4[(size_t)j0 * 32 + tid];
    }
    #pragma unroll
    for (int i = 0; i < 4; ++i) {             // W_in rows 32..63 = 1024 f4
        int e = tid + i * 256;
        w4[(e >> 5) * 33 + (e & 31)] = Wg4[1024 + e];
    }
    __syncthreads();

    {   // phase 1: one (j,y) per thread, 8 parallel FMA chains
        const int j = tid >> 5, y = tid & 31; // y == lane
        const float4* mr = m4 + j * 32;
        const float4* wr = w4 + y * 33;
        float4 A0 = make_float4(0.f, 0.f, 0.f, 0.f);
        float4 A1 = make_float4(0.f, 0.f, 0.f, 0.f);
        #pragma unroll
        for (int c = 0; c < 32; c += 2) DOT8(A0, A1, mr, wr, c);
        b_s[j * 32 + y] = ((A0.x + A0.y) + (A0.z + A0.w)
                         + (A1.x + A1.y) + (A1.z + A1.w)
                         + b_in[32 + y]) * op_mask[0];
    }
    CP_WAIT0();
    __syncthreads();

    // phase 2: C rows (8 j per thread-row), pre-scaled by op_norm
    const float opn = op_norm[0];
    const float* W_t = S + K12_WT;
    float4 wq[8];
    #pragma unroll
    for (int c = 0; c < 8; ++c)
        wq[c] = *(const float4*)(W_t + tid * 36 + c * 4);
    const float* wreg = (const float*)wq;

    float acc[8];
    #pragma unroll
    for (int j = 0; j < 8; ++j) acc[j] = 0.f;
    #pragma unroll
    for (int y = 0; y < 32; ++y) {
        float w = wreg[y];
        #pragma unroll
        for (int j = 0; j < 8; ++j) acc[j] += w * b_s[j * 32 + y];
    }

    const int row = rt * 256 + tid;           // row = p*32 + x
    #pragma unroll
    for (int j = 0; j < 8; ++j)
        g_Ch[(j0 + j) * 2048 + row] = __float2half_rn(acc[j] * opn);

    cudaTriggerProgrammaticLaunchCompletion();
}

// ---------------- kernel 3: Z = A @ C^T, M64 x N128 (R15 champion) + PDL ---
#define SROW 40
#define OA    0                           // 64 x 80 B = 5120
#define OB    5120                        // 128 x 80 B = 10240
#define OBIAS 15360                       // 256 B
#define OSTG  15616                       // 8 warps x 16 x 40 f32 = 20480 B
#define K3_SMEM (OSTG + 8 * 16 * 40 * 4)  // 36096

__global__ __launch_bounds__(256) void k3_gemm_mma(
        const float* __restrict__ b_out,
        const float* __restrict__ op_norm,
        float* __restrict__ out)
{
    extern __shared__ char smem[];
    __half* sA    = (__half*)(smem + OA);
    __half* sB    = (__half*)(smem + OB);
    float* s_bias = (float*)(smem + OBIAS);

    const int tid  = threadIdx.x;
    const int wid  = tid >> 5;
    const int lane = tid & 31;
    const int n0   = blockIdx.x * 128;
    const int m0   = blockIdx.y * 64;

    // independent prologue (inputs only), overlaps k12 tail under PDL
    if (tid < 64) s_bias[tid] = b_out[tid] * op_norm[0];

    cudaGridDependencySynchronize();     // wait for k12's g_Ah / g_Ch

    {   // A: 64 rows x 4 chunks = 256 -> one per thread
        int row = tid >> 2, ch = tid & 3;
        *(uint4*)(sA + row * SROW + ch * 8) =
            *(const uint4*)(g_Ah + (size_t)(m0 + row) * DHID + ch * 8);
    }
    #pragma unroll
    for (int i = 0; i < 2; ++i) {   // B: 128 rows x 4 chunks = 512
        int e = tid + i * 256;
        int row = e >> 2, ch = e & 3;
        *(uint4*)(sB + row * SROW + ch * 8) =
            *(const uint4*)(g_Ch + (size_t)(n0 + row) * DHID + ch * 8);
    }
    __syncthreads();

    const int warp_m = wid & 1;              // 32 rows
    const int warp_n = wid >> 1;             // 32 cols (0..3)

    const uint32_t a_b = smem_u32(sA);
    const uint32_t b_b = smem_u32(sB);

    const int cpair = (lane & 3) * 2;
    float D[2][4][4];
    #pragma unroll
    for (int nf = 0; nf < 4; ++nf) {
        int ncl = (warp_n & 1) * 32 + nf * 8 + cpair;   // p index (n0%128==0)
        float b0 = s_bias[ncl], b1 = s_bias[ncl + 1];
        #pragma unroll
        for (int mf = 0; mf < 2; ++mf) {
            D[mf][nf][0] = b0; D[mf][nf][1] = b1;
            D[mf][nf][2] = b0; D[mf][nf][3] = b1;
        }
    }

    #pragma unroll
    for (int ks = 0; ks < 2; ++ks) {
        const int kk = ks * 16;
        uint32_t A[2][4];
        #pragma unroll
        for (int mf = 0; mf < 2; ++mf) {
            int row = warp_m * 32 + mf * 16 + (lane & 15);
            int col = kk + (lane >> 4) * 8;
            ldsm_x4(A[mf], a_b + row * (SROW * 2) + col * 2);
        }
        int brow_c = (lane & 7) + ((lane >> 4) & 1) * 8;
        int bcol   = kk + (lane & 8);
        #pragma unroll
        for (int g = 0; g < 2; ++g) {        // each x4 covers 16 cols
            int brow = warp_n * 32 + g * 16 + brow_c;
            uint32_t B[4];
            ldsm_x4(B, b_b + brow * (SROW * 2) + bcol * 2);
            #pragma unroll
            for (int mf = 0; mf < 2; ++mf) {
                mma_f16(D[mf][2 * g],     A[mf], B);
                mma_f16(D[mf][2 * g + 1], A[mf], B + 2);
            }
        }
    }

    // ---- epilogue: warp-private stage -> full-line coalesced stores ----
    float* W = (float*)(smem + OSTG) + wid * (16 * 40);
    const int rgrp = lane >> 2;
    const int rr   = lane >> 3;          // 0..3
    const int cq   = (lane & 7) * 4;     // 0..28
    #pragma unroll
    for (int mf = 0; mf < 2; ++mf) {
        #pragma unroll
        for (int nf = 0; nf < 4; ++nf) {
            *(float2*)&W[rgrp * 40 + nf * 8 + cpair] =
                make_float2(D[mf][nf][0], D[mf][nf][1]);
            *(float2*)&W[(rgrp + 8) * 40 + nf * 8 + cpair] =
                make_float2(D[mf][nf][2], D[mf][nf][3]);
        }
        __syncwarp();
        #pragma unroll
        for (int rb = 0; rb < 4; ++rb) {
            int row = rb * 4 + rr;
            float4 v = *(const float4*)&W[row * 40 + cq];
            int gr = m0 + warp_m * 32 + mf * 16 + row;
            stcs4(out + (size_t)gr * NCOL + n0 + warp_n * 32 + cq, v);
        }
        __syncwarp();
    }
}

// ---------------- launch ---------------------------------------------------
extern "C" void kernel_launch(void* const* d_in, const int* in_sizes, int n_in,
                              void* d_out, int out_size)
{
    (void)in_sizes; (void)n_in; (void)out_size;
    const float* m       = (const float*)d_in[0];
    /* d_in[1] = nlist: unused by the reference */
    const float* op_mask = (const float*)d_in[2];
    const float* op_norm = (const float*)d_in[3];
    const float* W_in    = (const float*)d_in[4];
    const float* b_in    = (const float*)d_in[5];
    const float* W_out   = (const float*)d_in[6];
    const float* b_out   = (const float*)d_in[7];
    float* out = (float*)d_out;

    cudaFuncSetAttribute(k12, cudaFuncAttributeMaxDynamicSharedMemorySize, K12_SMEM);
    cudaFuncSetAttribute(k3_gemm_mma,
                         cudaFuncAttributeMaxDynamicSharedMemorySize, K3_SMEM);

    k12<<<408, 256, K12_SMEM>>>(m, W_in, b_in, op_mask, op_norm, W_out);

    // k3 with programmatic dependent launch: overlaps its ramp with k12 tail
    cudaLaunchConfig_t cfg = {};
    cfg.gridDim  = dim3(192, 6);
    cfg.blockDim = dim3(256);
    cfg.dynamicSmemBytes = K3_SMEM;
    cfg.stream = 0;
    cudaLaunchAttribute attrs[1];
    attrs[0].id = cudaLaunchAttributeProgrammaticStreamSerialization;
    attrs[0].val.programmaticStreamSerializationAllowed = 1;
    cfg.attrs = attrs;
    cfg.numAttrs = 1;
    cudaLaunchKernelEx(&cfg, k3_gemm_mma, b_out, op_norm, out);
}